// round 1
// baseline (speedup 1.0000x reference)
#include <cuda_runtime.h>
#include <cuda_bf16.h>

// GCNConv: out = scatter_dst( (x @ W^T)[src] * norm ) + b, with self-loops and
// symmetric deg^{-1/2} normalization.
//
// Pipeline (all on default stream, graph-capturable, allocation-free):
//   k_deg_init   : deg[i] = 1.0 (self-loop weight)
//   k_deg_acc    : deg[dst[e]] += ew[e]            (atomics, 640k)
//   k_dinv       : dinv[i] = rsqrt(deg[i])
//   k_gemm       : h = x @ W^T                     (tiled smem fp32)
//   k_selfloop   : out[i] = h[i]*dinv[i]^2 + b     (also initializes out)
//   k_scatter    : out[dst] += h[src]*dinv[src]*ew*dinv[dst]   (warp/edge atomics)

#define MAX_NODES 10000
#define D 128

__device__ float g_deg[MAX_NODES];
__device__ float g_dinv[MAX_NODES];
__device__ float g_h[(size_t)MAX_NODES * D];

// ---------------------------------------------------------------------------
__global__ void k_deg_init(int n) {
    int i = blockIdx.x * blockDim.x + threadIdx.x;
    if (i < n) g_deg[i] = 1.0f;  // self-loop weight
}

__global__ void k_deg_acc(const float* __restrict__ ew,
                          const int* __restrict__ dst, int e) {
    int i = blockIdx.x * blockDim.x + threadIdx.x;
    if (i < e) atomicAdd(&g_deg[dst[i]], ew[i]);
}

__global__ void k_dinv(int n) {
    int i = blockIdx.x * blockDim.x + threadIdx.x;
    if (i < n) {
        float d = g_deg[i];
        g_dinv[i] = (d > 0.0f) ? rsqrtf(d) : 0.0f;
    }
}

// ---------------------------------------------------------------------------
// h = x @ W^T.  x: [n,128] row-major, W: [128,128] row-major (out,in).
// Block: 256 threads, 32 nodes per block, K tiled by 32.
// Thread (d = t&127, half = t>>7) computes 16 nodes' output d.
__global__ void k_gemm(const float* __restrict__ x, const float* __restrict__ W,
                       int n) {
    constexpr int BN = 32;
    constexpr int KT = 32;
    __shared__ float xs[BN][KT + 1];
    __shared__ float Ws[D][KT + 1];

    int node0 = blockIdx.x * BN;
    int t = threadIdx.x;
    int d = t & 127;
    int half = t >> 7;

    float acc[16];
#pragma unroll
    for (int j = 0; j < 16; j++) acc[j] = 0.0f;

    for (int k0 = 0; k0 < D; k0 += KT) {
        for (int i = t; i < BN * KT; i += 256) {
            int nn = i / KT, kk = i % KT;
            int gn = node0 + nn;
            xs[nn][kk] = (gn < n) ? x[(size_t)gn * D + k0 + kk] : 0.0f;
        }
        for (int i = t; i < D * KT; i += 256) {
            int r = i / KT, kk = i % KT;
            Ws[r][kk] = W[(size_t)r * D + k0 + kk];
        }
        __syncthreads();
#pragma unroll
        for (int kk = 0; kk < KT; kk++) {
            float w = Ws[d][kk];
#pragma unroll
            for (int j = 0; j < 16; j++)
                acc[j] += xs[half * 16 + j][kk] * w;
        }
        __syncthreads();
    }
#pragma unroll
    for (int j = 0; j < 16; j++) {
        int gn = node0 + half * 16 + j;
        if (gn < n) g_h[(size_t)gn * D + d] = acc[j];
    }
}

// ---------------------------------------------------------------------------
// out[i] = h[i] * dinv[i]^2 + b  (self-loop contribution; initializes out).
__global__ void k_selfloop(const float* __restrict__ b, float* __restrict__ out,
                           int n) {
    int i = blockIdx.x * blockDim.x + threadIdx.x;  // one thread per element
    if (i >= n * D) return;
    int node = i >> 7;
    int d = i & 127;
    float s = g_dinv[node];
    out[i] = g_h[i] * s * s + b[d];
}

// ---------------------------------------------------------------------------
// One warp per edge: lane l handles elements [4l, 4l+4).
__global__ void k_scatter(const float* __restrict__ ew,
                          const int* __restrict__ src,
                          const int* __restrict__ dst,
                          float* __restrict__ out, int e) {
    int warp = (blockIdx.x * blockDim.x + threadIdx.x) >> 5;
    int lane = threadIdx.x & 31;
    if (warp >= e) return;

    int s = src[warp];
    int t = dst[warp];
    float norm = g_dinv[s] * ew[warp] * g_dinv[t];

    const float4* hp = (const float4*)(g_h + (size_t)s * D);
    float4 v = hp[lane];

    float* op = out + (size_t)t * D + lane * 4;
    atomicAdd(op + 0, v.x * norm);
    atomicAdd(op + 1, v.y * norm);
    atomicAdd(op + 2, v.z * norm);
    atomicAdd(op + 3, v.w * norm);
}

// ---------------------------------------------------------------------------
extern "C" void kernel_launch(void* const* d_in, const int* in_sizes, int n_in,
                              void* d_out, int out_size) {
    const float* x  = (const float*)d_in[0];   // [n, 128]
    const float* W  = (const float*)d_in[1];   // [128, 128]
    const float* b  = (const float*)d_in[2];   // [128]
    const float* ew = (const float*)d_in[3];   // [e]
    const int* eidx = (const int*)d_in[4];     // [2, e]
    float* out = (float*)d_out;

    int n = in_sizes[0] / D;
    int e = in_sizes[3];
    const int* src = eidx;
    const int* dst = eidx + e;

    k_deg_init<<<(n + 255) / 256, 256>>>(n);
    k_deg_acc<<<(e + 255) / 256, 256>>>(ew, dst, e);
    k_dinv<<<(n + 255) / 256, 256>>>(n);
    k_gemm<<<(n + 31) / 32, 256>>>(x, W, n);
    k_selfloop<<<(n * D + 255) / 256, 256>>>(b, out, n);
    // 8 warps (8 edges) per 256-thread block
    k_scatter<<<(e + 7) / 8, 256>>>(ew, src, dst, out, e);
}

// round 2
// speedup vs baseline: 2.1379x; 2.1379x over previous
#include <cuda_runtime.h>
#include <cuda_bf16.h>

// GCNConv, CSR-gather formulation (no fp atomics on the hot path):
//   deg[i]  = 1 + sum_{e: dst=i} ew[e]
//   dinv    = rsqrt(deg)
//   h_s     = (x @ W^T) * dinv[node]          (dinv[src] folded in)
//   CSR sort of edges by dst (count / scan / scatter)
//   out[i]  = dinv[i] * ( h_s[i] + sum_{e->i} h_s[src[e]] * ew[e] ) + b

#define MAX_NODES 10016
#define MAX_EDGES 650000
#define D 128

__device__ float g_deg[MAX_NODES];
__device__ float g_dinv[MAX_NODES];
__device__ float g_h[(size_t)MAX_NODES * D];   // h_s = (xW^T)*dinv
__device__ int   g_cnt[MAX_NODES];
__device__ int   g_off[MAX_NODES + 1];
__device__ int   g_cur[MAX_NODES];
__device__ int   g_ssrc[MAX_EDGES];
__device__ float g_sw[MAX_EDGES];

// ---------------------------------------------------------------------------
__global__ void k_init(int n) {
    int i = blockIdx.x * blockDim.x + threadIdx.x;
    if (i < n) { g_deg[i] = 1.0f; g_cnt[i] = 0; }
}

// Fused degree accumulation + per-dst edge histogram.
__global__ void k_deg_hist(const float* __restrict__ ew,
                           const int* __restrict__ dst, int e) {
    int i = blockIdx.x * blockDim.x + threadIdx.x;
    if (i < e) {
        int d = dst[i];
        atomicAdd(&g_deg[d], ew[i]);
        atomicAdd(&g_cnt[d], 1);
    }
}

__global__ void k_dinv(int n) {
    int i = blockIdx.x * blockDim.x + threadIdx.x;
    if (i < n) {
        float d = g_deg[i];
        g_dinv[i] = (d > 0.0f) ? rsqrtf(d) : 0.0f;
    }
}

// Single-block exclusive scan of g_cnt[0..n) -> g_off[0..n], g_cur copy.
__global__ void k_scan(int n) {
    __shared__ int buf[1024];
    __shared__ int carry;
    int tid = threadIdx.x;
    if (tid == 0) carry = 0;
    __syncthreads();
    for (int base = 0; base < n; base += 1024) {
        int i = base + tid;
        int v = (i < n) ? g_cnt[i] : 0;
        buf[tid] = v;
        __syncthreads();
#pragma unroll
        for (int off = 1; off < 1024; off <<= 1) {
            int t = (tid >= off) ? buf[tid - off] : 0;
            __syncthreads();
            buf[tid] += t;
            __syncthreads();
        }
        int excl = carry + buf[tid] - v;
        if (i < n) { g_off[i] = excl; g_cur[i] = excl; }
        __syncthreads();
        if (tid == 1023) carry += buf[1023];
        __syncthreads();
    }
    if (tid == 0) g_off[n] = carry;
}

// Edge scatter into CSR slots (cheap int atomics for the cursor).
__global__ void k_build(const float* __restrict__ ew,
                        const int* __restrict__ src,
                        const int* __restrict__ dst, int e) {
    int i = blockIdx.x * blockDim.x + threadIdx.x;
    if (i < e) {
        int p = atomicAdd(&g_cur[dst[i]], 1);
        g_ssrc[p] = src[i];
        g_sw[p] = ew[i];
    }
}

// ---------------------------------------------------------------------------
// h_s = (x @ W^T) * dinv[node].  Block tile: 64 nodes x 128 dims, BK=16.
// 256 threads; thread (r=t/32, c=t%32) computes 8 nodes x 4 dims.
#define BM 64
#define BK 16
#define XS_LD 68
#define WS_LD 132
__global__ void k_gemm(const float* __restrict__ x, const float* __restrict__ W,
                       int n) {
    __shared__ float xs[BK][XS_LD];
    __shared__ float ws[BK][WS_LD];
    int t = threadIdx.x;
    int c = t & 31;
    int r = t >> 5;
    int node0 = blockIdx.x * BM;

    float acc[8][4];
#pragma unroll
    for (int j = 0; j < 8; j++)
#pragma unroll
        for (int i = 0; i < 4; i++) acc[j][i] = 0.0f;

    for (int k0 = 0; k0 < D; k0 += BK) {
        // x tile: 64 nodes x 16 k, stored transposed
        {
            int nn = t >> 2;            // 0..63
            int ks = (t & 3) * 4;       // 0,4,8,12
            int gn = node0 + nn;
            float4 v = make_float4(0.f, 0.f, 0.f, 0.f);
            if (gn < n) v = *(const float4*)&x[(size_t)gn * D + k0 + ks];
            xs[ks + 0][nn] = v.x; xs[ks + 1][nn] = v.y;
            xs[ks + 2][nn] = v.z; xs[ks + 3][nn] = v.w;
        }
        // W tile: 128 dims x 16 k, stored transposed
#pragma unroll
        for (int q = 0; q < 2; q++) {
            int f = t * 2 + q;          // 0..511
            int dim = f >> 2;
            int ks = (f & 3) * 4;
            float4 v = *(const float4*)&W[(size_t)dim * D + k0 + ks];
            ws[ks + 0][dim] = v.x; ws[ks + 1][dim] = v.y;
            ws[ks + 2][dim] = v.z; ws[ks + 3][dim] = v.w;
        }
        __syncthreads();
#pragma unroll
        for (int kk = 0; kk < BK; kk++) {
            float4 wv = *(const float4*)&ws[kk][c * 4];
            float4 xa = *(const float4*)&xs[kk][r * 8];
            float4 xb = *(const float4*)&xs[kk][r * 8 + 4];
            float xn[8] = {xa.x, xa.y, xa.z, xa.w, xb.x, xb.y, xb.z, xb.w};
#pragma unroll
            for (int j = 0; j < 8; j++) {
                acc[j][0] += xn[j] * wv.x;
                acc[j][1] += xn[j] * wv.y;
                acc[j][2] += xn[j] * wv.z;
                acc[j][3] += xn[j] * wv.w;
            }
        }
        __syncthreads();
    }
#pragma unroll
    for (int j = 0; j < 8; j++) {
        int gn = node0 + r * 8 + j;
        if (gn < n) {
            float dv = g_dinv[gn];
            float4 o = make_float4(acc[j][0] * dv, acc[j][1] * dv,
                                   acc[j][2] * dv, acc[j][3] * dv);
            *(float4*)&g_h[(size_t)gn * D + c * 4] = o;
        }
    }
}

// ---------------------------------------------------------------------------
// One warp per destination node; 128-float accumulator in registers.
__global__ void k_aggregate(const float* __restrict__ b, float* __restrict__ out,
                            int n) {
    int node = blockIdx.x * (blockDim.x >> 5) + (threadIdx.x >> 5);
    int lane = threadIdx.x & 31;
    if (node >= n) return;

    const float4* __restrict__ h4 = (const float4*)g_h;
    float4 acc = h4[(size_t)node * 32 + lane];  // self-loop (weight 1)

    int i = g_off[node];
    int end = g_off[node + 1];
    // 4-edge batches for memory-level parallelism
    for (; i + 4 <= end; i += 4) {
        int s0 = g_ssrc[i + 0], s1 = g_ssrc[i + 1];
        int s2 = g_ssrc[i + 2], s3 = g_ssrc[i + 3];
        float w0 = g_sw[i + 0], w1 = g_sw[i + 1];
        float w2 = g_sw[i + 2], w3 = g_sw[i + 3];
        float4 v0 = h4[(size_t)s0 * 32 + lane];
        float4 v1 = h4[(size_t)s1 * 32 + lane];
        float4 v2 = h4[(size_t)s2 * 32 + lane];
        float4 v3 = h4[(size_t)s3 * 32 + lane];
        acc.x += v0.x * w0 + v1.x * w1 + v2.x * w2 + v3.x * w3;
        acc.y += v0.y * w0 + v1.y * w1 + v2.y * w2 + v3.y * w3;
        acc.z += v0.z * w0 + v1.z * w1 + v2.z * w2 + v3.z * w3;
        acc.w += v0.w * w0 + v1.w * w1 + v2.w * w2 + v3.w * w3;
    }
    for (; i < end; i++) {
        int s = g_ssrc[i];
        float w = g_sw[i];
        float4 v = h4[(size_t)s * 32 + lane];
        acc.x += v.x * w; acc.y += v.y * w;
        acc.z += v.z * w; acc.w += v.w * w;
    }

    float dv = g_dinv[node];
    float4 bb = ((const float4*)b)[lane];
    float4 o = make_float4(acc.x * dv + bb.x, acc.y * dv + bb.y,
                           acc.z * dv + bb.z, acc.w * dv + bb.w);
    ((float4*)out)[(size_t)node * 32 + lane] = o;
}

// ---------------------------------------------------------------------------
extern "C" void kernel_launch(void* const* d_in, const int* in_sizes, int n_in,
                              void* d_out, int out_size) {
    const float* x  = (const float*)d_in[0];   // [n, 128]
    const float* W  = (const float*)d_in[1];   // [128, 128]
    const float* b  = (const float*)d_in[2];   // [128]
    const float* ew = (const float*)d_in[3];   // [e]
    const int* eidx = (const int*)d_in[4];     // [2, e]
    float* out = (float*)d_out;

    int n = in_sizes[0] / D;
    int e = in_sizes[3];
    const int* src = eidx;
    const int* dst = eidx + e;

    k_init<<<(n + 255) / 256, 256>>>(n);
    k_deg_hist<<<(e + 255) / 256, 256>>>(ew, dst, e);
    k_dinv<<<(n + 255) / 256, 256>>>(n);
    k_scan<<<1, 1024>>>(n);
    k_gemm<<<(n + BM - 1) / BM, 256>>>(x, W, n);
    k_build<<<(e + 255) / 256, 256>>>(ew, src, dst, e);
    // 8 warps (8 nodes) per 256-thread block
    k_aggregate<<<(n + 7) / 8, 256>>>(b, out, n);
}

// round 3
// speedup vs baseline: 2.3806x; 1.1135x over previous
#include <cuda_runtime.h>
#include <cuda_bf16.h>

// GCNConv, CSR-gather formulation, no fp atomics anywhere:
//   cnt histogram (int atomics) -> fast 1-block scan -> packed edge scatter
//   deg from CSR weights -> dinv
//   h_s = (x @ W^T) * dinv[node]
//   out[i] = dinv[i]*(h_s[i] + sum h_s[src]*ew) + b

#define MAX_NODES 10016
#define MAX_EDGES 650000
#define D 128

__device__ float g_dinv[MAX_NODES];
__device__ float g_h[(size_t)MAX_NODES * D];
__device__ int   g_cnt[MAX_NODES];
__device__ int   g_off[MAX_NODES + 1];
__device__ int   g_cur[MAX_NODES];
__device__ int2  g_edge[MAX_EDGES];   // {src, float_bits(ew)}

// ---------------------------------------------------------------------------
__global__ void k_init(int n) {
    int i = blockIdx.x * blockDim.x + threadIdx.x;
    if (i < n) g_cnt[i] = 0;
}

__global__ void k_hist(const int* __restrict__ dst, int e) {
    int i = blockIdx.x * blockDim.x + threadIdx.x;
    if (i < e) atomicAdd(&g_cnt[dst[i]], 1);
}

// Single-block scan: 1024 threads x CHUNK elements, 2 barriers total.
#define CHUNK 10   // 1024*10 = 10240 >= MAX_NODES
__global__ void k_scan(int n) {
    int tid = threadIdx.x;
    int lane = tid & 31, wid = tid >> 5;
    int base = tid * CHUNK;

    int v[CHUNK];
    int sum = 0;
#pragma unroll
    for (int j = 0; j < CHUNK; j++) {
        int i = base + j;
        int c = (i < n) ? g_cnt[i] : 0;
        v[j] = sum;           // exclusive local prefix
        sum += c;
    }
    // warp inclusive scan of per-thread sums
    int s = sum;
#pragma unroll
    for (int o = 1; o < 32; o <<= 1) {
        int t = __shfl_up_sync(0xffffffffu, s, o);
        if (lane >= o) s += t;
    }
    __shared__ int wsum[32];
    if (lane == 31) wsum[wid] = s;
    __syncthreads();
    if (wid == 0) {
        int w = wsum[lane];
#pragma unroll
        for (int o = 1; o < 32; o <<= 1) {
            int t = __shfl_up_sync(0xffffffffu, w, o);
            if (lane >= o) w += t;
        }
        wsum[lane] = w;
    }
    __syncthreads();
    int excl = s - sum + (wid > 0 ? wsum[wid - 1] : 0);
#pragma unroll
    for (int j = 0; j < CHUNK; j++) {
        int i = base + j;
        if (i < n) { int o = excl + v[j]; g_off[i] = o; g_cur[i] = o; }
    }
    if (tid == 1023) g_off[n] = excl + sum;  // grand total
}

// Edge scatter into CSR slots; packed 8B store.
__global__ void k_build(const float* __restrict__ ew,
                        const int* __restrict__ src,
                        const int* __restrict__ dst, int e) {
    int i = blockIdx.x * blockDim.x + threadIdx.x;
    if (i < e) {
        int p = atomicAdd(&g_cur[dst[i]], 1);
        g_edge[p] = make_int2(src[i], __float_as_int(ew[i]));
    }
}

// deg[i] = 1 + sum of CSR weights; dinv = rsqrt(deg). One warp per node.
__global__ void k_dinv(int n) {
    int node = blockIdx.x * (blockDim.x >> 5) + (threadIdx.x >> 5);
    int lane = threadIdx.x & 31;
    if (node >= n) return;
    int beg = g_off[node], end = g_off[node + 1];
    float s = 0.0f;
    for (int i = beg + lane; i < end; i += 32)
        s += __int_as_float(g_edge[i].y);
#pragma unroll
    for (int o = 16; o > 0; o >>= 1)
        s += __shfl_xor_sync(0xffffffffu, s, o);
    if (lane == 0) g_dinv[node] = rsqrtf(1.0f + s);
}

// ---------------------------------------------------------------------------
// h_s = (x @ W^T) * dinv.  64 nodes x 128 dims per block, BK=16, 256 threads.
#define BM 64
#define BK 16
#define XS_LD 68
#define WS_LD 132
__global__ void k_gemm(const float* __restrict__ x, const float* __restrict__ W,
                       int n) {
    __shared__ float xs[BK][XS_LD];
    __shared__ float ws[BK][WS_LD];
    int t = threadIdx.x;
    int c = t & 31;
    int r = t >> 5;
    int node0 = blockIdx.x * BM;

    float acc[8][4];
#pragma unroll
    for (int j = 0; j < 8; j++)
#pragma unroll
        for (int i = 0; i < 4; i++) acc[j][i] = 0.0f;

    for (int k0 = 0; k0 < D; k0 += BK) {
        {
            int nn = t >> 2;
            int ks = (t & 3) * 4;
            int gn = node0 + nn;
            float4 v = make_float4(0.f, 0.f, 0.f, 0.f);
            if (gn < n) v = *(const float4*)&x[(size_t)gn * D + k0 + ks];
            xs[ks + 0][nn] = v.x; xs[ks + 1][nn] = v.y;
            xs[ks + 2][nn] = v.z; xs[ks + 3][nn] = v.w;
        }
#pragma unroll
        for (int q = 0; q < 2; q++) {
            int f = t * 2 + q;
            int dim = f >> 2;
            int ks = (f & 3) * 4;
            float4 v = *(const float4*)&W[(size_t)dim * D + k0 + ks];
            ws[ks + 0][dim] = v.x; ws[ks + 1][dim] = v.y;
            ws[ks + 2][dim] = v.z; ws[ks + 3][dim] = v.w;
        }
        __syncthreads();
#pragma unroll
        for (int kk = 0; kk < BK; kk++) {
            float4 wv = *(const float4*)&ws[kk][c * 4];
            float4 xa = *(const float4*)&xs[kk][r * 8];
            float4 xb = *(const float4*)&xs[kk][r * 8 + 4];
            float xn[8] = {xa.x, xa.y, xa.z, xa.w, xb.x, xb.y, xb.z, xb.w};
#pragma unroll
            for (int j = 0; j < 8; j++) {
                acc[j][0] += xn[j] * wv.x;
                acc[j][1] += xn[j] * wv.y;
                acc[j][2] += xn[j] * wv.z;
                acc[j][3] += xn[j] * wv.w;
            }
        }
        __syncthreads();
    }
#pragma unroll
    for (int j = 0; j < 8; j++) {
        int gn = node0 + r * 8 + j;
        if (gn < n) {
            float dv = g_dinv[gn];
            float4 o = make_float4(acc[j][0] * dv, acc[j][1] * dv,
                                   acc[j][2] * dv, acc[j][3] * dv);
            *(float4*)&g_h[(size_t)gn * D + c * 4] = o;
        }
    }
}

// ---------------------------------------------------------------------------
// One warp per destination node; 128-float accumulator in registers.
__global__ void k_aggregate(const float* __restrict__ b, float* __restrict__ out,
                            int n) {
    int node = blockIdx.x * (blockDim.x >> 5) + (threadIdx.x >> 5);
    int lane = threadIdx.x & 31;
    if (node >= n) return;

    const float4* __restrict__ h4 = (const float4*)g_h;
    float4 acc = h4[(size_t)node * 32 + lane];  // self-loop

    int i = g_off[node];
    int end = g_off[node + 1];
    for (; i + 4 <= end; i += 4) {
        int2 e0 = g_edge[i + 0], e1 = g_edge[i + 1];
        int2 e2 = g_edge[i + 2], e3 = g_edge[i + 3];
        float4 v0 = h4[(size_t)e0.x * 32 + lane];
        float4 v1 = h4[(size_t)e1.x * 32 + lane];
        float4 v2 = h4[(size_t)e2.x * 32 + lane];
        float4 v3 = h4[(size_t)e3.x * 32 + lane];
        float w0 = __int_as_float(e0.y), w1 = __int_as_float(e1.y);
        float w2 = __int_as_float(e2.y), w3 = __int_as_float(e3.y);
        acc.x += v0.x * w0 + v1.x * w1 + v2.x * w2 + v3.x * w3;
        acc.y += v0.y * w0 + v1.y * w1 + v2.y * w2 + v3.y * w3;
        acc.z += v0.z * w0 + v1.z * w1 + v2.z * w2 + v3.z * w3;
        acc.w += v0.w * w0 + v1.w * w1 + v2.w * w2 + v3.w * w3;
    }
    for (; i < end; i++) {
        int2 e0 = g_edge[i];
        float w = __int_as_float(e0.y);
        float4 v = h4[(size_t)e0.x * 32 + lane];
        acc.x += v.x * w; acc.y += v.y * w;
        acc.z += v.z * w; acc.w += v.w * w;
    }

    float dv = g_dinv[node];
    float4 bb = ((const float4*)b)[lane];
    float4 o = make_float4(acc.x * dv + bb.x, acc.y * dv + bb.y,
                           acc.z * dv + bb.z, acc.w * dv + bb.w);
    ((float4*)out)[(size_t)node * 32 + lane] = o;
}

// ---------------------------------------------------------------------------
extern "C" void kernel_launch(void* const* d_in, const int* in_sizes, int n_in,
                              void* d_out, int out_size) {
    const float* x  = (const float*)d_in[0];
    const float* W  = (const float*)d_in[1];
    const float* b  = (const float*)d_in[2];
    const float* ew = (const float*)d_in[3];
    const int* eidx = (const int*)d_in[4];
    float* out = (float*)d_out;

    int n = in_sizes[0] / D;
    int e = in_sizes[3];
    const int* src = eidx;
    const int* dst = eidx + e;

    k_init<<<(n + 255) / 256, 256>>>(n);
    k_hist<<<(e + 255) / 256, 256>>>(dst, e);
    k_scan<<<1, 1024>>>(n);
    k_build<<<(e + 255) / 256, 256>>>(ew, src, dst, e);
    k_dinv<<<(n + 7) / 8, 256>>>(n);
    k_gemm<<<(n + BM - 1) / BM, 256>>>(x, W, n);
    k_aggregate<<<(n + 7) / 8, 256>>>(b, out, n);
}

// round 4
// speedup vs baseline: 2.6471x; 1.1119x over previous
#include <cuda_runtime.h>
#include <cuda_bf16.h>

// GCNConv, CSR-gather formulation, no fp atomics, no atomic on build path:
//   k_init  : zero cnt
//   k_hist  : rank[i] = atomicAdd(cnt[dst[i]], 1)   (rank captured from histogram)
//   k_scan  : 1-block shfl scan -> off
//   k_build : edge[off[dst]+rank] = {src, ew}       (NO atomics)
//   k_dinv  : dinv = rsqrt(1 + sum CSR weights)     (warp reduce)
//   k_gemm  : h_s = (x @ W^T) * dinv[node]
//   k_agg   : out[i] = dinv[i]*(h_s[i] + sum h_s[src]*ew) + b

#define MAX_NODES 10016
#define MAX_EDGES 650000
#define D 128

__device__ float g_dinv[MAX_NODES];
__device__ float g_h[(size_t)MAX_NODES * D];
__device__ int   g_cnt[MAX_NODES];
__device__ int   g_off[MAX_NODES + 1];
__device__ int   g_rank[MAX_EDGES];
__device__ int2  g_edge[MAX_EDGES];   // {src, float_bits(ew)}

// ---------------------------------------------------------------------------
__global__ void k_init(int n) {
    int i = blockIdx.x * blockDim.x + threadIdx.x;
    if (i < n) g_cnt[i] = 0;
}

// Histogram; the atomic's return value IS the edge's within-node rank.
__global__ void k_hist(const int* __restrict__ dst, int e) {
    int i = blockIdx.x * blockDim.x + threadIdx.x;
    if (i < e) g_rank[i] = atomicAdd(&g_cnt[dst[i]], 1);
}

// Single-block scan: 1024 threads x CHUNK elements, 2 barriers total.
#define CHUNK 10   // 1024*10 = 10240 >= MAX_NODES
__global__ void k_scan(int n) {
    int tid = threadIdx.x;
    int lane = tid & 31, wid = tid >> 5;
    int base = tid * CHUNK;

    int v[CHUNK];
    int sum = 0;
#pragma unroll
    for (int j = 0; j < CHUNK; j++) {
        int i = base + j;
        int c = (i < n) ? g_cnt[i] : 0;
        v[j] = sum;           // exclusive local prefix
        sum += c;
    }
    int s = sum;
#pragma unroll
    for (int o = 1; o < 32; o <<= 1) {
        int t = __shfl_up_sync(0xffffffffu, s, o);
        if (lane >= o) s += t;
    }
    __shared__ int wsum[32];
    if (lane == 31) wsum[wid] = s;
    __syncthreads();
    if (wid == 0) {
        int w = wsum[lane];
#pragma unroll
        for (int o = 1; o < 32; o <<= 1) {
            int t = __shfl_up_sync(0xffffffffu, w, o);
            if (lane >= o) w += t;
        }
        wsum[lane] = w;
    }
    __syncthreads();
    int excl = s - sum + (wid > 0 ? wsum[wid - 1] : 0);
#pragma unroll
    for (int j = 0; j < CHUNK; j++) {
        int i = base + j;
        if (i < n) g_off[i] = excl + v[j];
    }
    if (tid == 1023) g_off[n] = excl + sum;
}

// Atomic-free CSR scatter: position = off[dst] + rank.
__global__ void k_build(const float* __restrict__ ew,
                        const int* __restrict__ src,
                        const int* __restrict__ dst, int e) {
    int i = blockIdx.x * blockDim.x + threadIdx.x;
    if (i < e) {
        int p = g_off[dst[i]] + g_rank[i];
        g_edge[p] = make_int2(src[i], __float_as_int(ew[i]));
    }
}

// deg[i] = 1 + sum of CSR weights; dinv = rsqrt(deg). One warp per node.
__global__ void k_dinv(int n) {
    int node = blockIdx.x * (blockDim.x >> 5) + (threadIdx.x >> 5);
    int lane = threadIdx.x & 31;
    if (node >= n) return;
    int beg = g_off[node], end = g_off[node + 1];
    float s = 0.0f;
    for (int i = beg + lane; i < end; i += 32)
        s += __int_as_float(g_edge[i].y);
#pragma unroll
    for (int o = 16; o > 0; o >>= 1)
        s += __shfl_xor_sync(0xffffffffu, s, o);
    if (lane == 0) g_dinv[node] = rsqrtf(1.0f + s);
}

// ---------------------------------------------------------------------------
// h_s = (x @ W^T) * dinv.  64 nodes x 128 dims per block, BK=16, 256 threads.
#define BM 64
#define BK 16
#define XS_LD 68
#define WS_LD 132
__global__ void k_gemm(const float* __restrict__ x, const float* __restrict__ W,
                       int n) {
    __shared__ float xs[BK][XS_LD];
    __shared__ float ws[BK][WS_LD];
    int t = threadIdx.x;
    int c = t & 31;
    int r = t >> 5;
    int node0 = blockIdx.x * BM;

    float acc[8][4];
#pragma unroll
    for (int j = 0; j < 8; j++)
#pragma unroll
        for (int i = 0; i < 4; i++) acc[j][i] = 0.0f;

    for (int k0 = 0; k0 < D; k0 += BK) {
        {
            int nn = t >> 2;
            int ks = (t & 3) * 4;
            int gn = node0 + nn;
            float4 v = make_float4(0.f, 0.f, 0.f, 0.f);
            if (gn < n) v = *(const float4*)&x[(size_t)gn * D + k0 + ks];
            xs[ks + 0][nn] = v.x; xs[ks + 1][nn] = v.y;
            xs[ks + 2][nn] = v.z; xs[ks + 3][nn] = v.w;
        }
#pragma unroll
        for (int q = 0; q < 2; q++) {
            int f = t * 2 + q;
            int dim = f >> 2;
            int ks = (f & 3) * 4;
            float4 v = *(const float4*)&W[(size_t)dim * D + k0 + ks];
            ws[ks + 0][dim] = v.x; ws[ks + 1][dim] = v.y;
            ws[ks + 2][dim] = v.z; ws[ks + 3][dim] = v.w;
        }
        __syncthreads();
#pragma unroll
        for (int kk = 0; kk < BK; kk++) {
            float4 wv = *(const float4*)&ws[kk][c * 4];
            float4 xa = *(const float4*)&xs[kk][r * 8];
            float4 xb = *(const float4*)&xs[kk][r * 8 + 4];
            float xn[8] = {xa.x, xa.y, xa.z, xa.w, xb.x, xb.y, xb.z, xb.w};
#pragma unroll
            for (int j = 0; j < 8; j++) {
                acc[j][0] += xn[j] * wv.x;
                acc[j][1] += xn[j] * wv.y;
                acc[j][2] += xn[j] * wv.z;
                acc[j][3] += xn[j] * wv.w;
            }
        }
        __syncthreads();
    }
#pragma unroll
    for (int j = 0; j < 8; j++) {
        int gn = node0 + r * 8 + j;
        if (gn < n) {
            float dv = g_dinv[gn];
            float4 o = make_float4(acc[j][0] * dv, acc[j][1] * dv,
                                   acc[j][2] * dv, acc[j][3] * dv);
            *(float4*)&g_h[(size_t)gn * D + c * 4] = o;
        }
    }
}

// ---------------------------------------------------------------------------
// One warp per destination node; 128-float accumulator in registers.
__global__ void k_aggregate(const float* __restrict__ b, float* __restrict__ out,
                            int n) {
    int node = blockIdx.x * (blockDim.x >> 5) + (threadIdx.x >> 5);
    int lane = threadIdx.x & 31;
    if (node >= n) return;

    const float4* __restrict__ h4 = (const float4*)g_h;
    float4 acc = h4[(size_t)node * 32 + lane];  // self-loop

    int i = g_off[node];
    int end = g_off[node + 1];
    for (; i + 4 <= end; i += 4) {
        int2 e0 = g_edge[i + 0], e1 = g_edge[i + 1];
        int2 e2 = g_edge[i + 2], e3 = g_edge[i + 3];
        float4 v0 = h4[(size_t)e0.x * 32 + lane];
        float4 v1 = h4[(size_t)e1.x * 32 + lane];
        float4 v2 = h4[(size_t)e2.x * 32 + lane];
        float4 v3 = h4[(size_t)e3.x * 32 + lane];
        float w0 = __int_as_float(e0.y), w1 = __int_as_float(e1.y);
        float w2 = __int_as_float(e2.y), w3 = __int_as_float(e3.y);
        acc.x += v0.x * w0 + v1.x * w1 + v2.x * w2 + v3.x * w3;
        acc.y += v0.y * w0 + v1.y * w1 + v2.y * w2 + v3.y * w3;
        acc.z += v0.z * w0 + v1.z * w1 + v2.z * w2 + v3.z * w3;
        acc.w += v0.w * w0 + v1.w * w1 + v2.w * w2 + v3.w * w3;
    }
    for (; i < end; i++) {
        int2 e0 = g_edge[i];
        float w = __int_as_float(e0.y);
        float4 v = h4[(size_t)e0.x * 32 + lane];
        acc.x += v.x * w; acc.y += v.y * w;
        acc.z += v.z * w; acc.w += v.w * w;
    }

    float dv = g_dinv[node];
    float4 bb = ((const float4*)b)[lane];
    float4 o = make_float4(acc.x * dv + bb.x, acc.y * dv + bb.y,
                           acc.z * dv + bb.z, acc.w * dv + bb.w);
    ((float4*)out)[(size_t)node * 32 + lane] = o;
}

// ---------------------------------------------------------------------------
extern "C" void kernel_launch(void* const* d_in, const int* in_sizes, int n_in,
                              void* d_out, int out_size) {
    const float* x  = (const float*)d_in[0];
    const float* W  = (const float*)d_in[1];
    const float* b  = (const float*)d_in[2];
    const float* ew = (const float*)d_in[3];
    const int* eidx = (const int*)d_in[4];
    float* out = (float*)d_out;

    int n = in_sizes[0] / D;
    int e = in_sizes[3];
    const int* src = eidx;
    const int* dst = eidx + e;

    k_init<<<(n + 255) / 256, 256>>>(n);
    k_hist<<<(e + 255) / 256, 256>>>(dst, e);
    k_scan<<<1, 1024>>>(n);
    k_build<<<(e + 255) / 256, 256>>>(ew, src, dst, e);
    k_dinv<<<(n + 7) / 8, 256>>>(n);
    k_gemm<<<(n + BM - 1) / BM, 256>>>(x, W, n);
    k_aggregate<<<(n + 7) / 8, 256>>>(b, out, n);
}

// round 5
// speedup vs baseline: 2.8890x; 1.0914x over previous
#include <cuda_runtime.h>
#include <cuda_bf16.h>

// GCNConv, CSR-gather formulation with graph-captured stream parallelism:
//
//   branch A (s1): k_gemm      h = x @ W^T                (raw, no scaling)
//   branch B (s2): k_degacc    deg = 1 + sum ew by dst    (float atomics)
//                  k_dinvc     dinv = rsqrt(deg)
//   branch C (s0): k_init -> k_hist(rank) -> k_scan -> [wait B] k_build
//                  (build folds dinv[src]*ew*dinv[dst] into stored weight)
//   join:          [wait A] k_aggregate
//                  out = h[i]*dinv[i]^2 + sum h[src]*w_full + b

#define MAX_NODES 10016
#define MAX_EDGES 650000
#define D 128

__device__ float g_deg[MAX_NODES];
__device__ float g_dinv[MAX_NODES];
__device__ float g_h[(size_t)MAX_NODES * D];
__device__ int   g_cnt[MAX_NODES];
__device__ int   g_off[MAX_NODES + 1];
__device__ int   g_rank[MAX_EDGES];
__device__ int2  g_edge[MAX_EDGES];   // {src, float_bits(dinv_s*ew*dinv_d)}

// ---------------------------------------------------------------------------
__global__ void k_init(int n) {
    int i = blockIdx.x * blockDim.x + threadIdx.x;
    if (i < n) { g_cnt[i] = 0; g_deg[i] = 1.0f; }
}

__global__ void k_degacc(const float* __restrict__ ew,
                         const int* __restrict__ dst, int e) {
    int i = blockIdx.x * blockDim.x + threadIdx.x;
    if (i < e) atomicAdd(&g_deg[dst[i]], ew[i]);
}

__global__ void k_dinvc(int n) {
    int i = blockIdx.x * blockDim.x + threadIdx.x;
    if (i < n) g_dinv[i] = rsqrtf(g_deg[i]);   // deg >= 1 always
}

// Histogram; atomic return value IS the edge's within-node rank.
__global__ void k_hist(const int* __restrict__ dst, int e) {
    int i = blockIdx.x * blockDim.x + threadIdx.x;
    if (i < e) g_rank[i] = atomicAdd(&g_cnt[dst[i]], 1);
}

// Single-block scan: 1024 threads x CHUNK elements, 2 barriers total.
#define CHUNK 10   // 1024*10 = 10240 >= MAX_NODES
__global__ void k_scan(int n) {
    int tid = threadIdx.x;
    int lane = tid & 31, wid = tid >> 5;
    int base = tid * CHUNK;

    int v[CHUNK];
    int sum = 0;
#pragma unroll
    for (int j = 0; j < CHUNK; j++) {
        int i = base + j;
        int c = (i < n) ? g_cnt[i] : 0;
        v[j] = sum;
        sum += c;
    }
    int s = sum;
#pragma unroll
    for (int o = 1; o < 32; o <<= 1) {
        int t = __shfl_up_sync(0xffffffffu, s, o);
        if (lane >= o) s += t;
    }
    __shared__ int wsum[32];
    if (lane == 31) wsum[wid] = s;
    __syncthreads();
    if (wid == 0) {
        int w = wsum[lane];
#pragma unroll
        for (int o = 1; o < 32; o <<= 1) {
            int t = __shfl_up_sync(0xffffffffu, w, o);
            if (lane >= o) w += t;
        }
        wsum[lane] = w;
    }
    __syncthreads();
    int excl = s - sum + (wid > 0 ? wsum[wid - 1] : 0);
#pragma unroll
    for (int j = 0; j < CHUNK; j++) {
        int i = base + j;
        if (i < n) g_off[i] = excl + v[j];
    }
    if (tid == 1023) g_off[n] = excl + sum;
}

// Atomic-free CSR scatter with fully folded edge weight.
__global__ void k_build(const float* __restrict__ ew,
                        const int* __restrict__ src,
                        const int* __restrict__ dst, int e) {
    int i = blockIdx.x * blockDim.x + threadIdx.x;
    if (i < e) {
        int s = src[i], d = dst[i];
        float w = g_dinv[s] * ew[i] * g_dinv[d];
        int p = g_off[d] + g_rank[i];
        g_edge[p] = make_int2(s, __float_as_int(w));
    }
}

// ---------------------------------------------------------------------------
// h = x @ W^T (raw).  64 nodes x 128 dims per block, BK=16, 256 threads.
#define BM 64
#define BK 16
#define XS_LD 68
#define WS_LD 132
__global__ void k_gemm(const float* __restrict__ x, const float* __restrict__ W,
                       int n) {
    __shared__ float xs[BK][XS_LD];
    __shared__ float ws[BK][WS_LD];
    int t = threadIdx.x;
    int c = t & 31;
    int r = t >> 5;
    int node0 = blockIdx.x * BM;

    float acc[8][4];
#pragma unroll
    for (int j = 0; j < 8; j++)
#pragma unroll
        for (int i = 0; i < 4; i++) acc[j][i] = 0.0f;

    for (int k0 = 0; k0 < D; k0 += BK) {
        {
            int nn = t >> 2;
            int ks = (t & 3) * 4;
            int gn = node0 + nn;
            float4 v = make_float4(0.f, 0.f, 0.f, 0.f);
            if (gn < n) v = *(const float4*)&x[(size_t)gn * D + k0 + ks];
            xs[ks + 0][nn] = v.x; xs[ks + 1][nn] = v.y;
            xs[ks + 2][nn] = v.z; xs[ks + 3][nn] = v.w;
        }
#pragma unroll
        for (int q = 0; q < 2; q++) {
            int f = t * 2 + q;
            int dim = f >> 2;
            int ks = (f & 3) * 4;
            float4 v = *(const float4*)&W[(size_t)dim * D + k0 + ks];
            ws[ks + 0][dim] = v.x; ws[ks + 1][dim] = v.y;
            ws[ks + 2][dim] = v.z; ws[ks + 3][dim] = v.w;
        }
        __syncthreads();
#pragma unroll
        for (int kk = 0; kk < BK; kk++) {
            float4 wv = *(const float4*)&ws[kk][c * 4];
            float4 xa = *(const float4*)&xs[kk][r * 8];
            float4 xb = *(const float4*)&xs[kk][r * 8 + 4];
            float xn[8] = {xa.x, xa.y, xa.z, xa.w, xb.x, xb.y, xb.z, xb.w};
#pragma unroll
            for (int j = 0; j < 8; j++) {
                acc[j][0] += xn[j] * wv.x;
                acc[j][1] += xn[j] * wv.y;
                acc[j][2] += xn[j] * wv.z;
                acc[j][3] += xn[j] * wv.w;
            }
        }
        __syncthreads();
    }
#pragma unroll
    for (int j = 0; j < 8; j++) {
        int gn = node0 + r * 8 + j;
        if (gn < n) {
            float4 o = make_float4(acc[j][0], acc[j][1], acc[j][2], acc[j][3]);
            *(float4*)&g_h[(size_t)gn * D + c * 4] = o;
        }
    }
}

// ---------------------------------------------------------------------------
// One warp per destination node; 128-float accumulator in registers.
__global__ void k_aggregate(const float* __restrict__ b, float* __restrict__ out,
                            int n) {
    int node = blockIdx.x * (blockDim.x >> 5) + (threadIdx.x >> 5);
    int lane = threadIdx.x & 31;
    if (node >= n) return;

    const float4* __restrict__ h4 = (const float4*)g_h;
    float dv = g_dinv[node];
    float sd = dv * dv;                  // self-loop weight dinv^2, ew=1
    float4 acc = h4[(size_t)node * 32 + lane];
    acc.x *= sd; acc.y *= sd; acc.z *= sd; acc.w *= sd;

    int i = g_off[node];
    int end = g_off[node + 1];
    for (; i + 4 <= end; i += 4) {
        int2 e0 = g_edge[i + 0], e1 = g_edge[i + 1];
        int2 e2 = g_edge[i + 2], e3 = g_edge[i + 3];
        float4 v0 = h4[(size_t)e0.x * 32 + lane];
        float4 v1 = h4[(size_t)e1.x * 32 + lane];
        float4 v2 = h4[(size_t)e2.x * 32 + lane];
        float4 v3 = h4[(size_t)e3.x * 32 + lane];
        float w0 = __int_as_float(e0.y), w1 = __int_as_float(e1.y);
        float w2 = __int_as_float(e2.y), w3 = __int_as_float(e3.y);
        acc.x += v0.x * w0 + v1.x * w1 + v2.x * w2 + v3.x * w3;
        acc.y += v0.y * w0 + v1.y * w1 + v2.y * w2 + v3.y * w3;
        acc.z += v0.z * w0 + v1.z * w1 + v2.z * w2 + v3.z * w3;
        acc.w += v0.w * w0 + v1.w * w1 + v2.w * w2 + v3.w * w3;
    }
    for (; i < end; i++) {
        int2 e0 = g_edge[i];
        float w = __int_as_float(e0.y);
        float4 v = h4[(size_t)e0.x * 32 + lane];
        acc.x += v.x * w; acc.y += v.y * w;
        acc.z += v.z * w; acc.w += v.w * w;
    }

    float4 bb = ((const float4*)b)[lane];
    float4 o = make_float4(acc.x + bb.x, acc.y + bb.y,
                           acc.z + bb.z, acc.w + bb.w);
    ((float4*)out)[(size_t)node * 32 + lane] = o;
}

// ---------------------------------------------------------------------------
extern "C" void kernel_launch(void* const* d_in, const int* in_sizes, int n_in,
                              void* d_out, int out_size) {
    const float* x  = (const float*)d_in[0];
    const float* W  = (const float*)d_in[1];
    const float* b  = (const float*)d_in[2];
    const float* ew = (const float*)d_in[3];
    const int* eidx = (const int*)d_in[4];
    float* out = (float*)d_out;

    int n = in_sizes[0] / D;
    int e = in_sizes[3];
    const int* src = eidx;
    const int* dst = eidx + e;

    // One-time host-side resources (no device memory involved).
    static cudaStream_t s1 = nullptr, s2 = nullptr;
    static cudaEvent_t ev_fork = nullptr, ev_gemm = nullptr,
                       ev_initdone = nullptr, ev_dinv = nullptr;
    if (s1 == nullptr) {
        cudaStreamCreateWithFlags(&s1, cudaStreamNonBlocking);
        cudaStreamCreateWithFlags(&s2, cudaStreamNonBlocking);
        cudaEventCreateWithFlags(&ev_fork, cudaEventDisableTiming);
        cudaEventCreateWithFlags(&ev_gemm, cudaEventDisableTiming);
        cudaEventCreateWithFlags(&ev_initdone, cudaEventDisableTiming);
        cudaEventCreateWithFlags(&ev_dinv, cudaEventDisableTiming);
    }

    // ---- branch A: gemm on s1 (depends only on x, W) ----
    cudaEventRecord(ev_fork, 0);
    cudaStreamWaitEvent(s1, ev_fork, 0);
    k_gemm<<<(n + BM - 1) / BM, 256, 0, s1>>>(x, W, n);
    cudaEventRecord(ev_gemm, s1);

    // ---- branch C head: init (zeroes cnt, deg=1) on main stream ----
    k_init<<<(n + 255) / 256, 256>>>(n);
    cudaEventRecord(ev_initdone, 0);

    // ---- branch B: degree + dinv on s2 ----
    cudaStreamWaitEvent(s2, ev_initdone, 0);
    k_degacc<<<(e + 255) / 256, 256, 0, s2>>>(ew, dst, e);
    k_dinvc<<<(n + 255) / 256, 256, 0, s2>>>(n);
    cudaEventRecord(ev_dinv, s2);

    // ---- branch C: hist -> scan -> (wait dinv) build ----
    k_hist<<<(e + 255) / 256, 256>>>(dst, e);
    k_scan<<<1, 1024>>>(n);
    cudaStreamWaitEvent(0, ev_dinv, 0);
    k_build<<<(e + 255) / 256, 256>>>(ew, src, dst, e);

    // ---- join A, then aggregate ----
    cudaStreamWaitEvent(0, ev_gemm, 0);
    k_aggregate<<<(n + 7) / 8, 256>>>(b, out, n);
}